// round 11
// baseline (speedup 1.0000x reference)
#include <cuda_runtime.h>

#define NB 8
#define NN 1024
#define NC 128
#define TI 32
#define TJ 32

typedef unsigned long long u64;

// q,k: [B,N,64] (g*16+d), v: [B,N,128] (l*16+d)
__device__ float g_q[NB * NN * 64];
__device__ float g_k[NB * NN * 64];
__device__ float g_v[NB * NN * 128];

// ---- f32x2 packed helpers (sm_103a) ----
__device__ __forceinline__ u64 pk(float lo, float hi) {
    u64 o; asm("mov.b64 %0, {%1, %2};" : "=l"(o) : "f"(lo), "f"(hi)); return o;
}
__device__ __forceinline__ void upk(u64 v, float& lo, float& hi) {
    asm("mov.b64 {%0, %1}, %2;" : "=f"(lo), "=f"(hi) : "l"(v));
}
__device__ __forceinline__ u64 m2(u64 a, u64 b) {
    u64 o; asm("mul.rn.f32x2 %0, %1, %2;" : "=l"(o) : "l"(a), "l"(b)); return o;
}
__device__ __forceinline__ void f2(u64& d, u64 a, u64 b) {
    asm("fma.rn.f32x2 %0, %1, %2, %0;" : "+l"(d) : "l"(a), "l"(b));
}

// ---------------------------------------------------------------------------
// Projection kernel (unchanged from R6 — register-tiled 4x4).
// ---------------------------------------------------------------------------
__global__ __launch_bounds__(256, 2) void proj_kernel(
    const float* __restrict__ x,
    const float* __restrict__ Wq,
    const float* __restrict__ Wk,
    const float* __restrict__ Wv)
{
    extern __shared__ float sm[];
    float* Wall = sm;                 // 128 rows x 132
    float* xs   = sm + 128 * 132;     // 32 x 128

    const int tid = threadIdx.x;
    const int h   = blockIdx.y;

    for (int idx = tid; idx < 128 * 128; idx += 256) {
        int r = idx >> 7, cc = idx & 127;
        int c = h * 128 + r;
        float val;
        if (c < 64)        val = Wq[c * 128 + cc];
        else if (c < 128)  val = Wk[(c - 64) * 128 + cc];
        else               val = Wv[(c - 128) * 128 + cc];
        Wall[r * 132 + cc] = val;
    }
    const int row0 = blockIdx.x * 32;
    for (int idx = tid; idx < 32 * 128; idx += 256)
        xs[idx] = x[row0 * 128 + idx];
    __syncthreads();

    const int tx = tid & 31;
    const int ty = tid >> 5;

    float acc[4][4];
    #pragma unroll
    for (int r = 0; r < 4; r++)
        #pragma unroll
        for (int u = 0; u < 4; u++) acc[r][u] = 0.f;

    #pragma unroll 4
    for (int k4 = 0; k4 < 32; k4++) {
        float4 w[4], xv[4];
        #pragma unroll
        for (int u = 0; u < 4; u++)
            w[u] = ((const float4*)(Wall + (tx + 32 * u) * 132))[k4];
        #pragma unroll
        for (int r = 0; r < 4; r++)
            xv[r] = ((const float4*)(xs + (ty * 4 + r) * 128))[k4];
        #pragma unroll
        for (int r = 0; r < 4; r++)
            #pragma unroll
            for (int u = 0; u < 4; u++)
                acc[r][u] += xv[r].x * w[u].x + xv[r].y * w[u].y
                           + xv[r].z * w[u].z + xv[r].w * w[u].w;
    }

    #pragma unroll
    for (int r = 0; r < 4; r++) {
        int row = row0 + ty * 4 + r;
        #pragma unroll
        for (int u = 0; u < 4; u++) {
            int cg = h * 128 + tx + 32 * u;
            float val = acc[r][u];
            if (cg < 64)        g_q[row * 64 + cg]          = val;
            else if (cg < 128)  g_k[row * 64 + (cg - 64)]   = val;
            else                g_v[row * 128 + (cg - 128)] = val;
        }
    }
}

// ---------------------------------------------------------------------------
// Fused attention. Grid (32,8)=256 CTAs of 256 threads, 87KB smem, 2 CTAs/SM.
// Row-pair-interleaved a_s/m_s layouts: phase B LDS.128 yields pre-packed
// f32x2 operands (zero mov.b64 packs).
//   a_s[rp][j][g][par], j-stride 12 floats (banks jA*12 mod 32 distinct)
//   m_s[rp][j][m][par], same stride
// Phase A: scalar dots, packs pairs for free in STS.128 register arrangement.
// Phase B: fully packed mix + fixed-shift exp + packed PV.
// ---------------------------------------------------------------------------
__global__ __launch_bounds__(256, 2) void attn_kernel(
    const float* __restrict__ masks,
    const float* __restrict__ mask_proj,
    float* __restrict__ out)
{
    extern __shared__ float sm[];
    float* q_s = sm;                         // 32*68   = 2176
    float* k_s = q_s + TI * 68;              // 32*68   = 2176
    float* v_s = k_s + TJ * 68;              // 32*160  = 5120 ([j][l*20+d])
    float* m_s = v_s + TJ * 160;             // 16*384  = 6144 ([rp][j*12+m*2+par])
    float* a_s = m_s + 16 * 384;             // 16*384  = 6144 ([rp][j*12+g*2+par])

    const int tid = threadIdx.x;
    const int b   = blockIdx.y;
    const int i0  = blockIdx.x * TI;

    // q tile (persistent)
    for (int idx = tid; idx < TI * 16; idx += 256) {
        int i = idx >> 4, c4 = idx & 15;
        ((float4*)(q_s + i * 68))[c4] =
            ((const float4*)g_q)[(b * NN + i0 + i) * 16 + c4];
    }

    // phase-A identity: key row jA, i-octant io (4 i's = rowpairs 2io, 2io+1)
    const int jA = tid & 31;
    const int io = tid >> 5;
    // phase-B identity: local head l, row pair rp, j half jh
    const int l  = tid & 7;
    const int rp = (tid >> 3) & 15;
    const int jh = tid >> 7;
    const int r0 = rp * 2;

    // Tm duplicated into packed registers
    u64 Tm2[3][4];
    #pragma unroll
    for (int m = 0; m < 3; m++)
        #pragma unroll
        for (int g = 0; g < 4; g++) {
            float t = mask_proj[m * 32 + g * 8 + l];
            Tm2[m][g] = pk(t, t);
        }

    float s0 = 0.f, s1 = 0.f;
    u64 acc0p[8], acc1p[8];
    #pragma unroll
    for (int d = 0; d < 8; d++) { acc0p[d] = 0ull; acc1p[d] = 0ull; }

    for (int t = 0; t < 32; t++) {
        const int j0 = t * TJ;
        __syncthreads();   // previous tile fully consumed

        // k tile
        for (int idx = tid; idx < TJ * 16; idx += 256) {
            int j = idx >> 4, c4 = idx & 15;
            ((float4*)(k_s + j * 68))[c4] =
                ((const float4*)g_k)[(b * NN + j0 + j) * 16 + c4];
        }
        // v tile -> [j][l*20+d]
        for (int idx = tid; idx < TJ * 32; idx += 256) {
            int j = idx >> 5, c4 = idx & 31;
            float4 val = ((const float4*)g_v)[(b * NN + j0 + j) * 32 + c4];
            *((float4*)(v_s + j * 160 + (c4 >> 2) * 20 + (c4 & 3) * 4)) = val;
        }
        // masks tile -> paired layout [i>>1][j*12 + m*2 + (i&1)]
        for (int idx = tid; idx < TI * 24; idx += 256) {
            int i  = idx / 24;
            int c4 = idx - i * 24;
            float4 val = *((const float4*)(masks + (size_t)(i0 + i) * 3072 + j0 * 3 + c4 * 4));
            float vv[4] = {val.x, val.y, val.z, val.w};
            float* mrow = m_s + (i >> 1) * 384 + (i & 1);
            #pragma unroll
            for (int e = 0; e < 4; e++) {
                int tc = c4 * 4 + e;
                int j  = tc / 3;
                int m  = tc - 3 * j;
                mrow[j * 12 + m * 2] = vv[e];
            }
        }
        __syncthreads();

        // ---- Phase A: thread (jA, io): scores for 4 i x 4 g, paired stores ----
        {
            float scr[4][4];
            #pragma unroll
            for (int g = 0; g < 4; g++) {
                const float4* kp = (const float4*)(k_s + jA * 68 + g * 16);
                float4 k0 = kp[0], k1 = kp[1], k2 = kp[2], k3 = kp[3];
                #pragma unroll
                for (int ii = 0; ii < 4; ii++) {
                    const float4* qp = (const float4*)(q_s + (io * 4 + ii) * 68 + g * 16);
                    float4 q0 = qp[0], q1 = qp[1], q2 = qp[2], q3 = qp[3];
                    scr[ii][g] =
                          q0.x * k0.x + q0.y * k0.y + q0.z * k0.z + q0.w * k0.w
                        + q1.x * k1.x + q1.y * k1.y + q1.z * k1.z + q1.w * k1.w
                        + q2.x * k2.x + q2.y * k2.y + q2.z * k2.z + q2.w * k2.w
                        + q3.x * k3.x + q3.y * k3.y + q3.z * k3.z + q3.w * k3.w;
                }
            }
            float* base0 = a_s + (io * 2)     * 384 + jA * 12;
            float* base1 = a_s + (io * 2 + 1) * 384 + jA * 12;
            ((float4*)base0)[0] = make_float4(scr[0][0], scr[1][0], scr[0][1], scr[1][1]);
            ((float4*)base0)[1] = make_float4(scr[0][2], scr[1][2], scr[0][3], scr[1][3]);
            ((float4*)base1)[0] = make_float4(scr[2][0], scr[3][0], scr[2][1], scr[3][1]);
            ((float4*)base1)[1] = make_float4(scr[2][2], scr[3][2], scr[2][3], scr[3][3]);
        }
        __syncthreads();

        // ---- Phase B: 2 rows x 16 j, pack-free f32x2 ----
        #pragma unroll 2
        for (int jj = 0; jj < 16; jj++) {
            int j = jh * 16 + jj;
            const ulonglong2* vp = (const ulonglong2*)(v_s + j * 160 + l * 20);
            ulonglong2 va = vp[0], vb = vp[1], vc = vp[2], vd = vp[3];

            const float* abase = a_s + rp * 384 + j * 12;
            const float* mbase = m_s + rp * 384 + j * 12;
            ulonglong2 a01 = *((const ulonglong2*)abase);
            ulonglong2 a23 = *((const ulonglong2*)(abase + 4));
            u64 pa0 = a01.x, pa1 = a01.y, pa2 = a23.x, pa3 = a23.y;
            ulonglong2 m01 = *((const ulonglong2*)mbase);
            u64 pm0 = m01.x, pm1 = m01.y;
            u64 pm2 = *((const u64*)(mbase + 4));

            u64 c0 = m2(pa0, Tm2[0][0]);
            f2(c0, pa1, Tm2[0][1]); f2(c0, pa2, Tm2[0][2]); f2(c0, pa3, Tm2[0][3]);
            u64 c1 = m2(pa0, Tm2[1][0]);
            f2(c1, pa1, Tm2[1][1]); f2(c1, pa2, Tm2[1][2]); f2(c1, pa3, Tm2[1][3]);
            u64 c2 = m2(pa0, Tm2[2][0]);
            f2(c2, pa1, Tm2[2][1]); f2(c2, pa2, Tm2[2][2]); f2(c2, pa3, Tm2[2][3]);

            u64 scp = m2(pm0, c0);
            f2(scp, pm1, c1); f2(scp, pm2, c2);

            float scA, scB;
            upk(scp, scA, scB);
            float e0 = __expf(scA - 8.0f);
            float e1 = __expf(scB - 8.0f);
            s0 += e0;
            s1 += e1;

            u64 ep0 = pk(e0, e0), ep1 = pk(e1, e1);
            f2(acc0p[0], ep0, va.x); f2(acc0p[1], ep0, va.y);
            f2(acc0p[2], ep0, vb.x); f2(acc0p[3], ep0, vb.y);
            f2(acc0p[4], ep0, vc.x); f2(acc0p[5], ep0, vc.y);
            f2(acc0p[6], ep0, vd.x); f2(acc0p[7], ep0, vd.y);
            f2(acc1p[0], ep1, va.x); f2(acc1p[1], ep1, va.y);
            f2(acc1p[2], ep1, vb.x); f2(acc1p[3], ep1, vb.y);
            f2(acc1p[4], ep1, vc.x); f2(acc1p[5], ep1, vc.y);
            f2(acc1p[6], ep1, vd.x); f2(acc1p[7], ep1, vd.y);
        }
    }

    // unpack accumulators
    float acc0[16], acc1[16];
    #pragma unroll
    for (int d = 0; d < 8; d++) {
        upk(acc0p[d], acc0[2 * d], acc0[2 * d + 1]);
        upk(acc1p[d], acc1[2 * d], acc1[2 * d + 1]);
    }

    // ---- exact cross-jh reduction (fixed-shift softmax = plain sum) ----
    __syncthreads();
    float* red = sm;   // overlays q_s/k_s/v_s (needs 4608 floats)
    if (jh == 1) {
        float* r = red + (tid - 128) * 36;
        #pragma unroll
        for (int d = 0; d < 16; d++) { r[d] = acc0[d]; r[16 + d] = acc1[d]; }
        r[32] = s0;
        r[33] = s1;
    }
    __syncthreads();
    if (jh == 0) {
        const float* r = red + tid * 36;
        #pragma unroll
        for (int d = 0; d < 16; d++) { acc0[d] += r[d]; acc1[d] += r[16 + d]; }
        s0 += r[32];
        s1 += r[33];

        float inv0 = 1.0f / s0;
        float inv1 = 1.0f / s1;
        float4* o0 = (float4*)(out + ((size_t)(b * NN + i0 + r0))     * 128 + l * 16);
        float4* o1 = (float4*)(out + ((size_t)(b * NN + i0 + r0 + 1)) * 128 + l * 16);
        o0[0] = make_float4(acc0[0]  * inv0, acc0[1]  * inv0, acc0[2]  * inv0, acc0[3]  * inv0);
        o0[1] = make_float4(acc0[4]  * inv0, acc0[5]  * inv0, acc0[6]  * inv0, acc0[7]  * inv0);
        o0[2] = make_float4(acc0[8]  * inv0, acc0[9]  * inv0, acc0[10] * inv0, acc0[11] * inv0);
        o0[3] = make_float4(acc0[12] * inv0, acc0[13] * inv0, acc0[14] * inv0, acc0[15] * inv0);
        o1[0] = make_float4(acc1[0]  * inv1, acc1[1]  * inv1, acc1[2]  * inv1, acc1[3]  * inv1);
        o1[1] = make_float4(acc1[4]  * inv1, acc1[5]  * inv1, acc1[6]  * inv1, acc1[7]  * inv1);
        o1[2] = make_float4(acc1[8]  * inv1, acc1[9]  * inv1, acc1[10] * inv1, acc1[11] * inv1);
        o1[3] = make_float4(acc1[12] * inv1, acc1[13] * inv1, acc1[14] * inv1, acc1[15] * inv1);
    }
}

extern "C" void kernel_launch(void* const* d_in, const int* in_sizes, int n_in,
                              void* d_out, int out_size)
{
    (void)in_sizes; (void)n_in; (void)out_size;
    const float* x     = (const float*)d_in[0];
    const float* masks = (const float*)d_in[1];
    const float* Wq    = (const float*)d_in[2];
    const float* Wk    = (const float*)d_in[3];
    const float* Wv    = (const float*)d_in[4];
    const float* mp    = (const float*)d_in[5];
    float* out = (float*)d_out;

    const size_t smP = (size_t)(128 * 132 + 32 * 128) * sizeof(float);          // 83968 B
    const size_t smA = (size_t)(TI * 68 + TJ * 68 + TJ * 160 + 16 * 384 * 2)
                       * sizeof(float);                                          // 87040 B
    cudaFuncSetAttribute(proj_kernel, cudaFuncAttributeMaxDynamicSharedMemorySize, (int)smP);
    cudaFuncSetAttribute(attn_kernel, cudaFuncAttributeMaxDynamicSharedMemorySize, (int)smA);

    proj_kernel<<<dim3(256, 2), 256, smP>>>(x, Wq, Wk, Wv);
    attn_kernel<<<dim3(NN / TI, NB), 256, smA>>>(masks, mp, out);
}

// round 12
// speedup vs baseline: 1.2042x; 1.2042x over previous
#include <cuda_runtime.h>

#define NB 8
#define NN 1024
#define NC 128
#define TI 32
#define TJ 32

// q,k: [B,N,64] (g*16+d), v: [B,N,128] (l*16+d)
__device__ float g_q[NB * NN * 64];
__device__ float g_k[NB * NN * 64];
__device__ float g_v[NB * NN * 128];

// ---------------------------------------------------------------------------
// Projection kernel (R6 register-tiled 4x4, best measured).
// ---------------------------------------------------------------------------
__global__ __launch_bounds__(256, 2) void proj_kernel(
    const float* __restrict__ x,
    const float* __restrict__ Wq,
    const float* __restrict__ Wk,
    const float* __restrict__ Wv)
{
    extern __shared__ float sm[];
    float* Wall = sm;                 // 128 rows x 132
    float* xs   = sm + 128 * 132;     // 32 x 128

    const int tid = threadIdx.x;
    const int h   = blockIdx.y;

    for (int idx = tid; idx < 128 * 128; idx += 256) {
        int r = idx >> 7, cc = idx & 127;
        int c = h * 128 + r;
        float val;
        if (c < 64)        val = Wq[c * 128 + cc];
        else if (c < 128)  val = Wk[(c - 64) * 128 + cc];
        else               val = Wv[(c - 128) * 128 + cc];
        Wall[r * 132 + cc] = val;
    }
    const int row0 = blockIdx.x * 32;
    for (int idx = tid; idx < 32 * 128; idx += 256)
        xs[idx] = x[row0 * 128 + idx];
    __syncthreads();

    const int tx = tid & 31;
    const int ty = tid >> 5;

    float acc[4][4];
    #pragma unroll
    for (int r = 0; r < 4; r++)
        #pragma unroll
        for (int u = 0; u < 4; u++) acc[r][u] = 0.f;

    #pragma unroll 4
    for (int k4 = 0; k4 < 32; k4++) {
        float4 w[4], xv[4];
        #pragma unroll
        for (int u = 0; u < 4; u++)
            w[u] = ((const float4*)(Wall + (tx + 32 * u) * 132))[k4];
        #pragma unroll
        for (int r = 0; r < 4; r++)
            xv[r] = ((const float4*)(xs + (ty * 4 + r) * 128))[k4];
        #pragma unroll
        for (int r = 0; r < 4; r++)
            #pragma unroll
            for (int u = 0; u < 4; u++)
                acc[r][u] += xv[r].x * w[u].x + xv[r].y * w[u].y
                           + xv[r].z * w[u].z + xv[r].w * w[u].w;
    }

    #pragma unroll
    for (int r = 0; r < 4; r++) {
        int row = row0 + ty * 4 + r;
        #pragma unroll
        for (int u = 0; u < 4; u++) {
            int cg = h * 128 + tx + 32 * u;
            float val = acc[r][u];
            if (cg < 64)        g_q[row * 64 + cg]          = val;
            else if (cg < 128)  g_k[row * 64 + (cg - 64)]   = val;
            else                g_v[row * 128 + (cg - 128)] = val;
        }
    }
}

// ---------------------------------------------------------------------------
// Fused attention (R5 scalar skeleton — best measured inner loop) with
// GMEM loads hoisted above the consuming barrier: LDGs go to registers
// while the previous tile is still being computed, hiding load latency.
// Grid (32,8)=256 CTAs of 256 threads, 71.7KB smem, 2 CTAs/SM.
// ---------------------------------------------------------------------------
__global__ __launch_bounds__(256, 2) void attn_kernel(
    const float* __restrict__ masks,
    const float* __restrict__ mask_proj,
    float* __restrict__ out)
{
    extern __shared__ float sm[];
    float* q_s = sm;                         // 32*68
    float* k_s = q_s + TI * 68;              // 32*68
    float* v_s = k_s + TJ * 68;              // 32*160 ([j][l*20+d])
    float* m_s = v_s + TJ * 160;             // 32*132 ([i][j*4+m])
    float* a_s = m_s + TI * 132;             // 32*132 ([i][j*4+g])

    const int tid = threadIdx.x;
    const int b   = blockIdx.y;
    const int i0  = blockIdx.x * TI;

    // q tile (persistent)
    for (int idx = tid; idx < TI * 16; idx += 256) {
        int i = idx >> 4, c4 = idx & 15;
        ((float4*)(q_s + i * 68))[c4] =
            ((const float4*)g_q)[(b * NN + i0 + i) * 16 + c4];
    }

    // phase-A identity: key row jA, i-octant io (4 i's)
    const int jA = tid & 31;
    const int io = tid >> 5;
    // phase-B identity: local head l, row pair rp, j half jh
    const int l  = tid & 7;
    const int rp = (tid >> 3) & 15;
    const int jh = tid >> 7;
    const int r0 = rp * 2;

    float Tm[3][4];
    #pragma unroll
    for (int m = 0; m < 3; m++)
        #pragma unroll
        for (int g = 0; g < 4; g++)
            Tm[m][g] = mask_proj[m * 32 + g * 8 + l];

    float s0 = 0.f, s1 = 0.f;
    float acc0[16], acc1[16];
    #pragma unroll
    for (int d = 0; d < 16; d++) { acc0[d] = 0.f; acc1[d] = 0.f; }

    for (int t = 0; t < 32; t++) {
        const int j0 = t * TJ;

        // ---- prefetch tile t into REGISTERS (no smem touch) ----
        // k: 2 float4, v: 4 float4, masks: 3 float4 per thread
        float4 kreg[2], vreg[4], mreg[3];
        #pragma unroll
        for (int it = 0; it < 2; it++) {
            int idx = tid + 256 * it;
            int j = idx >> 4, c4 = idx & 15;
            kreg[it] = ((const float4*)g_k)[(b * NN + j0 + j) * 16 + c4];
        }
        #pragma unroll
        for (int it = 0; it < 4; it++) {
            int idx = tid + 256 * it;
            int j = idx >> 5, c4 = idx & 31;
            vreg[it] = ((const float4*)g_v)[(b * NN + j0 + j) * 32 + c4];
        }
        #pragma unroll
        for (int it = 0; it < 3; it++) {
            int idx = tid + 256 * it;
            int i  = idx / 24;
            int c4 = idx - i * 24;
            mreg[it] = *((const float4*)(masks + (size_t)(i0 + i) * 3072 + j0 * 3 + c4 * 4));
        }

        __syncthreads();   // previous tile fully consumed

        // ---- store prefetched registers to smem ----
        #pragma unroll
        for (int it = 0; it < 2; it++) {
            int idx = tid + 256 * it;
            int j = idx >> 4, c4 = idx & 15;
            ((float4*)(k_s + j * 68))[c4] = kreg[it];
        }
        #pragma unroll
        for (int it = 0; it < 4; it++) {
            int idx = tid + 256 * it;
            int j = idx >> 5, c4 = idx & 31;
            *((float4*)(v_s + j * 160 + (c4 >> 2) * 20 + (c4 & 3) * 4)) = vreg[it];
        }
        #pragma unroll
        for (int it = 0; it < 3; it++) {
            int idx = tid + 256 * it;
            int i  = idx / 24;
            int c4 = idx - i * 24;
            float vv[4] = {mreg[it].x, mreg[it].y, mreg[it].z, mreg[it].w};
            #pragma unroll
            for (int e = 0; e < 4; e++) {
                int tc = c4 * 4 + e;
                int j  = tc / 3;
                int m  = tc - 3 * j;
                m_s[i * 132 + j * 4 + m] = vv[e];
            }
        }
        __syncthreads();

        // ---- Phase A: thread (jA, io): scores for 4 i x 4 g ----
        {
            float scr[4][4];
            #pragma unroll
            for (int g = 0; g < 4; g++) {
                const float4* kp = (const float4*)(k_s + jA * 68 + g * 16);
                float4 k0 = kp[0], k1 = kp[1], k2 = kp[2], k3 = kp[3];
                #pragma unroll
                for (int ii = 0; ii < 4; ii++) {
                    const float4* qp = (const float4*)(q_s + (io * 4 + ii) * 68 + g * 16);
                    float4 q0 = qp[0], q1 = qp[1], q2 = qp[2], q3 = qp[3];
                    scr[ii][g] =
                          q0.x * k0.x + q0.y * k0.y + q0.z * k0.z + q0.w * k0.w
                        + q1.x * k1.x + q1.y * k1.y + q1.z * k1.z + q1.w * k1.w
                        + q2.x * k2.x + q2.y * k2.y + q2.z * k2.z + q2.w * k2.w
                        + q3.x * k3.x + q3.y * k3.y + q3.z * k3.z + q3.w * k3.w;
                }
            }
            #pragma unroll
            for (int ii = 0; ii < 4; ii++)
                *((float4*)(a_s + (io * 4 + ii) * 132 + jA * 4)) =
                    make_float4(scr[ii][0], scr[ii][1], scr[ii][2], scr[ii][3]);
        }
        __syncthreads();

        // ---- Phase B: 2 rows x 16 j (scalar — best measured) ----
        #pragma unroll 4
        for (int jj = 0; jj < 16; jj++) {
            int j = jh * 16 + jj;
            const float4* vp = (const float4*)(v_s + j * 160 + l * 20);
            float4 v0 = vp[0], v1 = vp[1], v2 = vp[2], v3 = vp[3];

            float4 aa0 = *((const float4*)(a_s + r0 * 132 + j * 4));
            float4 mk0 = *((const float4*)(m_s + r0 * 132 + j * 4));
            float4 aa1 = *((const float4*)(a_s + (r0 + 1) * 132 + j * 4));
            float4 mk1 = *((const float4*)(m_s + (r0 + 1) * 132 + j * 4));

            float c0 = aa0.x * Tm[0][0] + aa0.y * Tm[0][1] + aa0.z * Tm[0][2] + aa0.w * Tm[0][3];
            float c1 = aa0.x * Tm[1][0] + aa0.y * Tm[1][1] + aa0.z * Tm[1][2] + aa0.w * Tm[1][3];
            float c2 = aa0.x * Tm[2][0] + aa0.y * Tm[2][1] + aa0.z * Tm[2][2] + aa0.w * Tm[2][3];
            float scA = mk0.x * c0 + mk0.y * c1 + mk0.z * c2;

            float d0 = aa1.x * Tm[0][0] + aa1.y * Tm[0][1] + aa1.z * Tm[0][2] + aa1.w * Tm[0][3];
            float d1 = aa1.x * Tm[1][0] + aa1.y * Tm[1][1] + aa1.z * Tm[1][2] + aa1.w * Tm[1][3];
            float d2 = aa1.x * Tm[2][0] + aa1.y * Tm[2][1] + aa1.z * Tm[2][2] + aa1.w * Tm[2][3];
            float scB = mk1.x * d0 + mk1.y * d1 + mk1.z * d2;

            float e0 = __expf(scA - 8.0f);
            float e1 = __expf(scB - 8.0f);
            s0 += e0;
            s1 += e1;
            acc0[0]  += e0 * v0.x; acc0[1]  += e0 * v0.y; acc0[2]  += e0 * v0.z; acc0[3]  += e0 * v0.w;
            acc0[4]  += e0 * v1.x; acc0[5]  += e0 * v1.y; acc0[6]  += e0 * v1.z; acc0[7]  += e0 * v1.w;
            acc0[8]  += e0 * v2.x; acc0[9]  += e0 * v2.y; acc0[10] += e0 * v2.z; acc0[11] += e0 * v2.w;
            acc0[12] += e0 * v3.x; acc0[13] += e0 * v3.y; acc0[14] += e0 * v3.z; acc0[15] += e0 * v3.w;
            acc1[0]  += e1 * v0.x; acc1[1]  += e1 * v0.y; acc1[2]  += e1 * v0.z; acc1[3]  += e1 * v0.w;
            acc1[4]  += e1 * v1.x; acc1[5]  += e1 * v1.y; acc1[6]  += e1 * v1.z; acc1[7]  += e1 * v1.w;
            acc1[8]  += e1 * v2.x; acc1[9]  += e1 * v2.y; acc1[10] += e1 * v2.z; acc1[11] += e1 * v2.w;
            acc1[12] += e1 * v3.x; acc1[13] += e1 * v3.y; acc1[14] += e1 * v3.z; acc1[15] += e1 * v3.w;
        }
    }

    // ---- exact cross-jh reduction (fixed-shift softmax = plain sum) ----
    __syncthreads();
    float* red = sm;
    if (jh == 1) {
        float* r = red + (tid - 128) * 36;
        #pragma unroll
        for (int d = 0; d < 16; d++) { r[d] = acc0[d]; r[16 + d] = acc1[d]; }
        r[32] = s0;
        r[33] = s1;
    }
    __syncthreads();
    if (jh == 0) {
        const float* r = red + tid * 36;
        #pragma unroll
        for (int d = 0; d < 16; d++) { acc0[d] += r[d]; acc1[d] += r[16 + d]; }
        s0 += r[32];
        s1 += r[33];

        float inv0 = 1.0f / s0;
        float inv1 = 1.0f / s1;
        float4* o0 = (float4*)(out + ((size_t)(b * NN + i0 + r0))     * 128 + l * 16);
        float4* o1 = (float4*)(out + ((size_t)(b * NN + i0 + r0 + 1)) * 128 + l * 16);
        o0[0] = make_float4(acc0[0]  * inv0, acc0[1]  * inv0, acc0[2]  * inv0, acc0[3]  * inv0);
        o0[1] = make_float4(acc0[4]  * inv0, acc0[5]  * inv0, acc0[6]  * inv0, acc0[7]  * inv0);
        o0[2] = make_float4(acc0[8]  * inv0, acc0[9]  * inv0, acc0[10] * inv0, acc0[11] * inv0);
        o0[3] = make_float4(acc0[12] * inv0, acc0[13] * inv0, acc0[14] * inv0, acc0[15] * inv0);
        o1[0] = make_float4(acc1[0]  * inv1, acc1[1]  * inv1, acc1[2]  * inv1, acc1[3]  * inv1);
        o1[1] = make_float4(acc1[4]  * inv1, acc1[5]  * inv1, acc1[6]  * inv1, acc1[7]  * inv1);
        o1[2] = make_float4(acc1[8]  * inv1, acc1[9]  * inv1, acc1[10] * inv1, acc1[11] * inv1);
        o1[3] = make_float4(acc1[12] * inv1, acc1[13] * inv1, acc1[14] * inv1, acc1[15] * inv1);
    }
}

extern "C" void kernel_launch(void* const* d_in, const int* in_sizes, int n_in,
                              void* d_out, int out_size)
{
    (void)in_sizes; (void)n_in; (void)out_size;
    const float* x     = (const float*)d_in[0];
    const float* masks = (const float*)d_in[1];
    const float* Wq    = (const float*)d_in[2];
    const float* Wk    = (const float*)d_in[3];
    const float* Wv    = (const float*)d_in[4];
    const float* mp    = (const float*)d_in[5];
    float* out = (float*)d_out;

    const size_t smP = (size_t)(128 * 132 + 32 * 128) * sizeof(float);   // 83968 B
    const size_t smA = (size_t)(TI * 68 + TJ * 68 + TJ * 160 + TI * 132 + TI * 132)
                       * sizeof(float);                                  // 71680 B
    cudaFuncSetAttribute(proj_kernel, cudaFuncAttributeMaxDynamicSharedMemorySize, (int)smP);
    cudaFuncSetAttribute(attn_kernel, cudaFuncAttributeMaxDynamicSharedMemorySize, (int)smA);

    proj_kernel<<<dim3(256, 2), 256, smP>>>(x, Wq, Wk, Wv);
    attn_kernel<<<dim3(NN / TI, NB), 256, smA>>>(masks, mp, out);
}

// round 14
// speedup vs baseline: 1.2672x; 1.0522x over previous
#include <cuda_runtime.h>

#define NB 8
#define NN 1024
#define NC 128
#define TI 32
#define TJ 32

// q,k: [B,N,64] (g*16+d), v: [B,N,128] (l*16+d)
__device__ float g_q[NB * NN * 64];
__device__ float g_k[NB * NN * 64];
__device__ float g_v[NB * NN * 128];

// ---------------------------------------------------------------------------
// Projection kernel: grid (128 row-tiles of 64, 2 col-halves) = 256 CTAs,
// 256 threads, 100.4KB smem -> 2 CTAs/SM -> SINGLE WAVE (256 <= 296).
// W loaded once per CTA, amortized over two 32-row halves.
// Register-tiled 4 rows x 4 cols per thread (bank-clean, as measured in R6).
// ---------------------------------------------------------------------------
__global__ __launch_bounds__(256, 2) void proj_kernel(
    const float* __restrict__ x,
    const float* __restrict__ Wq,
    const float* __restrict__ Wk,
    const float* __restrict__ Wv)
{
    extern __shared__ float sm[];
    float* Wall = sm;                 // 128 rows x 132
    float* xs   = sm + 128 * 132;     // 64 x 128

    const int tid = threadIdx.x;
    const int h   = blockIdx.y;
    const int row0 = blockIdx.x * 64;

    // W: 128x128 floats as float4
    for (int idx = tid; idx < 128 * 32; idx += 256) {
        int r = idx >> 5, c4 = idx & 31;
        int c = h * 128 + r;
        const float* src;
        if (c < 64)        src = Wq + c * 128;
        else if (c < 128)  src = Wk + (c - 64) * 128;
        else               src = Wv + (c - 128) * 128;
        ((float4*)(Wall + r * 132))[c4] = ((const float4*)src)[c4];
    }
    // x: 64x128 floats as float4
    for (int idx = tid; idx < 64 * 32; idx += 256)
        ((float4*)xs)[idx] = ((const float4*)(x + (size_t)row0 * 128))[idx];
    __syncthreads();

    const int tx = tid & 31;          // col group
    const int ty = tid >> 5;          // row group within half

    #pragma unroll
    for (int rh = 0; rh < 2; rh++) {
        float acc[4][4];
        #pragma unroll
        for (int r = 0; r < 4; r++)
            #pragma unroll
            for (int u = 0; u < 4; u++) acc[r][u] = 0.f;

        const int rbase_s = rh * 32 + ty * 4;

        #pragma unroll 4
        for (int k4 = 0; k4 < 32; k4++) {
            float4 w[4], xv[4];
            #pragma unroll
            for (int u = 0; u < 4; u++)
                w[u] = ((const float4*)(Wall + (tx + 32 * u) * 132))[k4];
            #pragma unroll
            for (int r = 0; r < 4; r++)
                xv[r] = ((const float4*)(xs + (rbase_s + r) * 128))[k4];
            #pragma unroll
            for (int r = 0; r < 4; r++)
                #pragma unroll
                for (int u = 0; u < 4; u++)
                    acc[r][u] += xv[r].x * w[u].x + xv[r].y * w[u].y
                               + xv[r].z * w[u].z + xv[r].w * w[u].w;
        }

        #pragma unroll
        for (int r = 0; r < 4; r++) {
            int row = row0 + rbase_s + r;
            #pragma unroll
            for (int u = 0; u < 4; u++) {
                int cg = h * 128 + tx + 32 * u;
                float val = acc[r][u];
                if (cg < 64)        g_q[row * 64 + cg]          = val;
                else if (cg < 128)  g_k[row * 64 + (cg - 64)]   = val;
                else                g_v[row * 128 + (cg - 128)] = val;
            }
        }
    }
}

// ---------------------------------------------------------------------------
// Fused attention — UNCHANGED from R12 best (206.3us measured).
// Grid (32,8)=256 CTAs of 256 threads, 71.7KB smem, 2 CTAs/SM.
// Register prefetch of next tile above the consuming barrier.
// ---------------------------------------------------------------------------
__global__ __launch_bounds__(256, 2) void attn_kernel(
    const float* __restrict__ masks,
    const float* __restrict__ mask_proj,
    float* __restrict__ out)
{
    extern __shared__ float sm[];
    float* q_s = sm;                         // 32*68
    float* k_s = q_s + TI * 68;              // 32*68
    float* v_s = k_s + TJ * 68;              // 32*160 ([j][l*20+d])
    float* m_s = v_s + TJ * 160;             // 32*132 ([i][j*4+m])
    float* a_s = m_s + TI * 132;             // 32*132 ([i][j*4+g])

    const int tid = threadIdx.x;
    const int b   = blockIdx.y;
    const int i0  = blockIdx.x * TI;

    // q tile (persistent)
    for (int idx = tid; idx < TI * 16; idx += 256) {
        int i = idx >> 4, c4 = idx & 15;
        ((float4*)(q_s + i * 68))[c4] =
            ((const float4*)g_q)[(b * NN + i0 + i) * 16 + c4];
    }

    // phase-A identity: key row jA, i-octant io (4 i's)
    const int jA = tid & 31;
    const int io = tid >> 5;
    // phase-B identity: local head l, row pair rp, j half jh
    const int l  = tid & 7;
    const int rp = (tid >> 3) & 15;
    const int jh = tid >> 7;
    const int r0 = rp * 2;

    float Tm[3][4];
    #pragma unroll
    for (int m = 0; m < 3; m++)
        #pragma unroll
        for (int g = 0; g < 4; g++)
            Tm[m][g] = mask_proj[m * 32 + g * 8 + l];

    float s0 = 0.f, s1 = 0.f;
    float acc0[16], acc1[16];
    #pragma unroll
    for (int d = 0; d < 16; d++) { acc0[d] = 0.f; acc1[d] = 0.f; }

    for (int t = 0; t < 32; t++) {
        const int j0 = t * TJ;

        // ---- prefetch tile t into REGISTERS (no smem touch) ----
        float4 kreg[2], vreg[4], mreg[3];
        #pragma unroll
        for (int it = 0; it < 2; it++) {
            int idx = tid + 256 * it;
            int j = idx >> 4, c4 = idx & 15;
            kreg[it] = ((const float4*)g_k)[(b * NN + j0 + j) * 16 + c4];
        }
        #pragma unroll
        for (int it = 0; it < 4; it++) {
            int idx = tid + 256 * it;
            int j = idx >> 5, c4 = idx & 31;
            vreg[it] = ((const float4*)g_v)[(b * NN + j0 + j) * 32 + c4];
        }
        #pragma unroll
        for (int it = 0; it < 3; it++) {
            int idx = tid + 256 * it;
            int i  = idx / 24;
            int c4 = idx - i * 24;
            mreg[it] = *((const float4*)(masks + (size_t)(i0 + i) * 3072 + j0 * 3 + c4 * 4));
        }

        __syncthreads();   // previous tile fully consumed

        // ---- store prefetched registers to smem ----
        #pragma unroll
        for (int it = 0; it < 2; it++) {
            int idx = tid + 256 * it;
            int j = idx >> 4, c4 = idx & 15;
            ((float4*)(k_s + j * 68))[c4] = kreg[it];
        }
        #pragma unroll
        for (int it = 0; it < 4; it++) {
            int idx = tid + 256 * it;
            int j = idx >> 5, c4 = idx & 31;
            *((float4*)(v_s + j * 160 + (c4 >> 2) * 20 + (c4 & 3) * 4)) = vreg[it];
        }
        #pragma unroll
        for (int it = 0; it < 3; it++) {
            int idx = tid + 256 * it;
            int i  = idx / 24;
            int c4 = idx - i * 24;
            float vv[4] = {mreg[it].x, mreg[it].y, mreg[it].z, mreg[it].w};
            #pragma unroll
            for (int e = 0; e < 4; e++) {
                int tc = c4 * 4 + e;
                int j  = tc / 3;
                int m  = tc - 3 * j;
                m_s[i * 132 + j * 4 + m] = vv[e];
            }
        }
        __syncthreads();

        // ---- Phase A: thread (jA, io): scores for 4 i x 4 g ----
        {
            float scr[4][4];
            #pragma unroll
            for (int g = 0; g < 4; g++) {
                const float4* kp = (const float4*)(k_s + jA * 68 + g * 16);
                float4 k0 = kp[0], k1 = kp[1], k2 = kp[2], k3 = kp[3];
                #pragma unroll
                for (int ii = 0; ii < 4; ii++) {
                    const float4* qp = (const float4*)(q_s + (io * 4 + ii) * 68 + g * 16);
                    float4 q0 = qp[0], q1 = qp[1], q2 = qp[2], q3 = qp[3];
                    scr[ii][g] =
                          q0.x * k0.x + q0.y * k0.y + q0.z * k0.z + q0.w * k0.w
                        + q1.x * k1.x + q1.y * k1.y + q1.z * k1.z + q1.w * k1.w
                        + q2.x * k2.x + q2.y * k2.y + q2.z * k2.z + q2.w * k2.w
                        + q3.x * k3.x + q3.y * k3.y + q3.z * k3.z + q3.w * k3.w;
                }
            }
            #pragma unroll
            for (int ii = 0; ii < 4; ii++)
                *((float4*)(a_s + (io * 4 + ii) * 132 + jA * 4)) =
                    make_float4(scr[ii][0], scr[ii][1], scr[ii][2], scr[ii][3]);
        }
        __syncthreads();

        // ---- Phase B: 2 rows x 16 j ----
        #pragma unroll 4
        for (int jj = 0; jj < 16; jj++) {
            int j = jh * 16 + jj;
            const float4* vp = (const float4*)(v_s + j * 160 + l * 20);
            float4 v0 = vp[0], v1 = vp[1], v2 = vp[2], v3 = vp[3];

            float4 aa0 = *((const float4*)(a_s + r0 * 132 + j * 4));
            float4 mk0 = *((const float4*)(m_s + r0 * 132 + j * 4));
            float4 aa1 = *((const float4*)(a_s + (r0 + 1) * 132 + j * 4));
            float4 mk1 = *((const float4*)(m_s + (r0 + 1) * 132 + j * 4));

            float c0 = aa0.x * Tm[0][0] + aa0.y * Tm[0][1] + aa0.z * Tm[0][2] + aa0.w * Tm[0][3];
            float c1 = aa0.x * Tm[1][0] + aa0.y * Tm[1][1] + aa0.z * Tm[1][2] + aa0.w * Tm[1][3];
            float c2 = aa0.x * Tm[2][0] + aa0.y * Tm[2][1] + aa0.z * Tm[2][2] + aa0.w * Tm[2][3];
            float scA = mk0.x * c0 + mk0.y * c1 + mk0.z * c2;

            float d0 = aa1.x * Tm[0][0] + aa1.y * Tm[0][1] + aa1.z * Tm[0][2] + aa1.w * Tm[0][3];
            float d1 = aa1.x * Tm[1][0] + aa1.y * Tm[1][1] + aa1.z * Tm[1][2] + aa1.w * Tm[1][3];
            float d2 = aa1.x * Tm[2][0] + aa1.y * Tm[2][1] + aa1.z * Tm[2][2] + aa1.w * Tm[2][3];
            float scB = mk1.x * d0 + mk1.y * d1 + mk1.z * d2;

            float e0 = __expf(scA - 8.0f);
            float e1 = __expf(scB - 8.0f);
            s0 += e0;
            s1 += e1;
            acc0[0]  += e0 * v0.x; acc0[1]  += e0 * v0.y; acc0[2]  += e0 * v0.z; acc0[3]  += e0 * v0.w;
            acc0[4]  += e0 * v1.x; acc0[5]  += e0 * v1.y; acc0[6]  += e0 * v1.z; acc0[7]  += e0 * v1.w;
            acc0[8]  += e0 * v2.x; acc0[9]  += e0 * v2.y; acc0[10] += e0 * v2.z; acc0[11] += e0 * v2.w;
            acc0[12] += e0 * v3.x; acc0[13] += e0 * v3.y; acc0[14] += e0 * v3.z; acc0[15] += e0 * v3.w;
            acc1[0]  += e1 * v0.x; acc1[1]  += e1 * v0.y; acc1[2]  += e1 * v0.z; acc1[3]  += e1 * v0.w;
            acc1[4]  += e1 * v1.x; acc1[5]  += e1 * v1.y; acc1[6]  += e1 * v1.z; acc1[7]  += e1 * v1.w;
            acc1[8]  += e1 * v2.x; acc1[9]  += e1 * v2.y; acc1[10] += e1 * v2.z; acc1[11] += e1 * v2.w;
            acc1[12] += e1 * v3.x; acc1[13] += e1 * v3.y; acc1[14] += e1 * v3.z; acc1[15] += e1 * v3.w;
        }
    }

    // ---- exact cross-jh reduction (fixed-shift softmax = plain sum) ----
    __syncthreads();
    float* red = sm;
    if (jh == 1) {
        float* r = red + (tid - 128) * 36;
        #pragma unroll
        for (int d = 0; d < 16; d++) { r[d] = acc0[d]; r[16 + d] = acc1[d]; }
        r[32] = s0;
        r[33] = s1;
    }
    __syncthreads();
    if (jh == 0) {
        const float* r = red + tid * 36;
        #pragma unroll
        for (int d = 0; d < 16; d++) { acc0[d] += r[d]; acc1[d] += r[16 + d]; }
        s0 += r[32];
        s1 += r[33];

        float inv0 = 1.0f / s0;
        float inv1 = 1.0f / s1;
        float4* o0 = (float4*)(out + ((size_t)(b * NN + i0 + r0))     * 128 + l * 16);
        float4* o1 = (float4*)(out + ((size_t)(b * NN + i0 + r0 + 1)) * 128 + l * 16);
        o0[0] = make_float4(acc0[0]  * inv0, acc0[1]  * inv0, acc0[2]  * inv0, acc0[3]  * inv0);
        o0[1] = make_float4(acc0[4]  * inv0, acc0[5]  * inv0, acc0[6]  * inv0, acc0[7]  * inv0);
        o0[2] = make_float4(acc0[8]  * inv0, acc0[9]  * inv0, acc0[10] * inv0, acc0[11] * inv0);
        o0[3] = make_float4(acc0[12] * inv0, acc0[13] * inv0, acc0[14] * inv0, acc0[15] * inv0);
        o1[0] = make_float4(acc1[0]  * inv1, acc1[1]  * inv1, acc1[2]  * inv1, acc1[3]  * inv1);
        o1[1] = make_float4(acc1[4]  * inv1, acc1[5]  * inv1, acc1[6]  * inv1, acc1[7]  * inv1);
        o1[2] = make_float4(acc1[8]  * inv1, acc1[9]  * inv1, acc1[10] * inv1, acc1[11] * inv1);
        o1[3] = make_float4(acc1[12] * inv1, acc1[13] * inv1, acc1[14] * inv1, acc1[15] * inv1);
    }
}

extern "C" void kernel_launch(void* const* d_in, const int* in_sizes, int n_in,
                              void* d_out, int out_size)
{
    (void)in_sizes; (void)n_in; (void)out_size;
    const float* x     = (const float*)d_in[0];
    const float* masks = (const float*)d_in[1];
    const float* Wq    = (const float*)d_in[2];
    const float* Wk    = (const float*)d_in[3];
    const float* Wv    = (const float*)d_in[4];
    const float* mp    = (const float*)d_in[5];
    float* out = (float*)d_out;

    const size_t smP = (size_t)(128 * 132 + 64 * 128) * sizeof(float);   // 100352 B
    const size_t smA = (size_t)(TI * 68 + TJ * 68 + TJ * 160 + TI * 132 + TI * 132)
                       * sizeof(float);                                  // 71680 B
    cudaFuncSetAttribute(proj_kernel, cudaFuncAttributeMaxDynamicSharedMemorySize, (int)smP);
    cudaFuncSetAttribute(attn_kernel, cudaFuncAttributeMaxDynamicSharedMemorySize, (int)smA);

    proj_kernel<<<dim3(128, 2), 256, smP>>>(x, Wq, Wk, Wv);
    attn_kernel<<<dim3(NN / TI, NB), 256, smA>>>(masks, mp, out);
}

// round 15
// speedup vs baseline: 1.3476x; 1.0634x over previous
#include <cuda_runtime.h>

#define NB 8
#define NN 1024
#define NC 128
#define TI 32
#define TJ 32

typedef unsigned long long u64;

// q,k: [B,N,64] (g*16+d), v: [B,N,128] (l*16+d)
__device__ float g_q[NB * NN * 64];
__device__ float g_k[NB * NN * 64];
__device__ float g_v[NB * NN * 128];

// ---- f32x2 packed helpers (sm_103a) ----
__device__ __forceinline__ u64 pkdup(float v) {
    u64 o; asm("mov.b64 %0, {%1, %1};" : "=l"(o) : "f"(v)); return o;
}
__device__ __forceinline__ void upk(u64 v, float& lo, float& hi) {
    asm("mov.b64 {%0, %1}, %2;" : "=f"(lo), "=f"(hi) : "l"(v));
}
__device__ __forceinline__ void f2(u64& d, u64 a, u64 b) {
    asm("fma.rn.f32x2 %0, %1, %2, %0;" : "+l"(d) : "l"(a), "l"(b));
}

// ---------------------------------------------------------------------------
// Projection kernel — UNCHANGED from R14 best (single wave, 64 rows/CTA).
// ---------------------------------------------------------------------------
__global__ __launch_bounds__(256, 2) void proj_kernel(
    const float* __restrict__ x,
    const float* __restrict__ Wq,
    const float* __restrict__ Wk,
    const float* __restrict__ Wv)
{
    extern __shared__ float sm[];
    float* Wall = sm;                 // 128 rows x 132
    float* xs   = sm + 128 * 132;     // 64 x 128

    const int tid = threadIdx.x;
    const int h   = blockIdx.y;
    const int row0 = blockIdx.x * 64;

    for (int idx = tid; idx < 128 * 32; idx += 256) {
        int r = idx >> 5, c4 = idx & 31;
        int c = h * 128 + r;
        const float* src;
        if (c < 64)        src = Wq + c * 128;
        else if (c < 128)  src = Wk + (c - 64) * 128;
        else               src = Wv + (c - 128) * 128;
        ((float4*)(Wall + r * 132))[c4] = ((const float4*)src)[c4];
    }
    for (int idx = tid; idx < 64 * 32; idx += 256)
        ((float4*)xs)[idx] = ((const float4*)(x + (size_t)row0 * 128))[idx];
    __syncthreads();

    const int tx = tid & 31;
    const int ty = tid >> 5;

    #pragma unroll
    for (int rh = 0; rh < 2; rh++) {
        float acc[4][4];
        #pragma unroll
        for (int r = 0; r < 4; r++)
            #pragma unroll
            for (int u = 0; u < 4; u++) acc[r][u] = 0.f;

        const int rbase_s = rh * 32 + ty * 4;

        #pragma unroll 4
        for (int k4 = 0; k4 < 32; k4++) {
            float4 w[4], xv[4];
            #pragma unroll
            for (int u = 0; u < 4; u++)
                w[u] = ((const float4*)(Wall + (tx + 32 * u) * 132))[k4];
            #pragma unroll
            for (int r = 0; r < 4; r++)
                xv[r] = ((const float4*)(xs + (rbase_s + r) * 128))[k4];
            #pragma unroll
            for (int r = 0; r < 4; r++)
                #pragma unroll
                for (int u = 0; u < 4; u++)
                    acc[r][u] += xv[r].x * w[u].x + xv[r].y * w[u].y
                               + xv[r].z * w[u].z + xv[r].w * w[u].w;
        }

        #pragma unroll
        for (int r = 0; r < 4; r++) {
            int row = row0 + rbase_s + r;
            #pragma unroll
            for (int u = 0; u < 4; u++) {
                int cg = h * 128 + tx + 32 * u;
                float val = acc[r][u];
                if (cg < 64)        g_q[row * 64 + cg]          = val;
                else if (cg < 128)  g_k[row * 64 + (cg - 64)]   = val;
                else                g_v[row * 128 + (cg - 128)] = val;
            }
        }
    }
}

// ---------------------------------------------------------------------------
// Fused attention — R12/R14 skeleton, with two surgical changes in phase B:
//  (1) PV accumulation in packed f32x2 (v loaded as ulonglong2, e dup'd once)
//  (2) exp2 folding: Tm pre-scaled by log2e, shift folded into first sc FMA,
//      e = exp2f(sc) -> bare MUFU.EX2.
// Everything else (layout, identities, prefetch, barriers) byte-identical.
// ---------------------------------------------------------------------------
__global__ __launch_bounds__(256, 2) void attn_kernel(
    const float* __restrict__ masks,
    const float* __restrict__ mask_proj,
    float* __restrict__ out)
{
    extern __shared__ float sm[];
    float* q_s = sm;                         // 32*68
    float* k_s = q_s + TI * 68;              // 32*68
    float* v_s = k_s + TJ * 68;              // 32*160 ([j][l*20+d])
    float* m_s = v_s + TJ * 160;             // 32*132 ([i][j*4+m])
    float* a_s = m_s + TI * 132;             // 32*132 ([i][j*4+g])

    const int tid = threadIdx.x;
    const int b   = blockIdx.y;
    const int i0  = blockIdx.x * TI;

    // q tile (persistent)
    for (int idx = tid; idx < TI * 16; idx += 256) {
        int i = idx >> 4, c4 = idx & 15;
        ((float4*)(q_s + i * 68))[c4] =
            ((const float4*)g_q)[(b * NN + i0 + i) * 16 + c4];
    }

    // phase-A identity: key row jA, i-octant io (4 i's)
    const int jA = tid & 31;
    const int io = tid >> 5;
    // phase-B identity: local head l, row pair rp, j half jh
    const int l  = tid & 7;
    const int rp = (tid >> 3) & 15;
    const int jh = tid >> 7;
    const int r0 = rp * 2;

    // Tm pre-scaled by log2(e); exp shift folded as SHIFT2 = -8*log2(e)
    const float LOG2E  = 1.4426950408889634f;
    const float SHIFT2 = -8.0f * LOG2E;
    float Tm[3][4];
    #pragma unroll
    for (int m = 0; m < 3; m++)
        #pragma unroll
        for (int g = 0; g < 4; g++)
            Tm[m][g] = mask_proj[m * 32 + g * 8 + l] * LOG2E;

    float s0 = 0.f, s1 = 0.f;
    u64 acc0p[8], acc1p[8];
    #pragma unroll
    for (int d = 0; d < 8; d++) { acc0p[d] = 0ull; acc1p[d] = 0ull; }

    for (int t = 0; t < 32; t++) {
        const int j0 = t * TJ;

        // ---- prefetch tile t into REGISTERS (no smem touch) ----
        float4 kreg[2], vreg[4], mreg[3];
        #pragma unroll
        for (int it = 0; it < 2; it++) {
            int idx = tid + 256 * it;
            int j = idx >> 4, c4 = idx & 15;
            kreg[it] = ((const float4*)g_k)[(b * NN + j0 + j) * 16 + c4];
        }
        #pragma unroll
        for (int it = 0; it < 4; it++) {
            int idx = tid + 256 * it;
            int j = idx >> 5, c4 = idx & 31;
            vreg[it] = ((const float4*)g_v)[(b * NN + j0 + j) * 32 + c4];
        }
        #pragma unroll
        for (int it = 0; it < 3; it++) {
            int idx = tid + 256 * it;
            int i  = idx / 24;
            int c4 = idx - i * 24;
            mreg[it] = *((const float4*)(masks + (size_t)(i0 + i) * 3072 + j0 * 3 + c4 * 4));
        }

        __syncthreads();   // previous tile fully consumed

        // ---- store prefetched registers to smem ----
        #pragma unroll
        for (int it = 0; it < 2; it++) {
            int idx = tid + 256 * it;
            int j = idx >> 4, c4 = idx & 15;
            ((float4*)(k_s + j * 68))[c4] = kreg[it];
        }
        #pragma unroll
        for (int it = 0; it < 4; it++) {
            int idx = tid + 256 * it;
            int j = idx >> 5, c4 = idx & 31;
            *((float4*)(v_s + j * 160 + (c4 >> 2) * 20 + (c4 & 3) * 4)) = vreg[it];
        }
        #pragma unroll
        for (int it = 0; it < 3; it++) {
            int idx = tid + 256 * it;
            int i  = idx / 24;
            int c4 = idx - i * 24;
            float vv[4] = {mreg[it].x, mreg[it].y, mreg[it].z, mreg[it].w};
            #pragma unroll
            for (int e = 0; e < 4; e++) {
                int tc = c4 * 4 + e;
                int j  = tc / 3;
                int m  = tc - 3 * j;
                m_s[i * 132 + j * 4 + m] = vv[e];
            }
        }
        __syncthreads();

        // ---- Phase A: thread (jA, io): scores for 4 i x 4 g ----
        {
            float scr[4][4];
            #pragma unroll
            for (int g = 0; g < 4; g++) {
                const float4* kp = (const float4*)(k_s + jA * 68 + g * 16);
                float4 k0 = kp[0], k1 = kp[1], k2 = kp[2], k3 = kp[3];
                #pragma unroll
                for (int ii = 0; ii < 4; ii++) {
                    const float4* qp = (const float4*)(q_s + (io * 4 + ii) * 68 + g * 16);
                    float4 q0 = qp[0], q1 = qp[1], q2 = qp[2], q3 = qp[3];
                    scr[ii][g] =
                          q0.x * k0.x + q0.y * k0.y + q0.z * k0.z + q0.w * k0.w
                        + q1.x * k1.x + q1.y * k1.y + q1.z * k1.z + q1.w * k1.w
                        + q2.x * k2.x + q2.y * k2.y + q2.z * k2.z + q2.w * k2.w
                        + q3.x * k3.x + q3.y * k3.y + q3.z * k3.z + q3.w * k3.w;
                }
            }
            #pragma unroll
            for (int ii = 0; ii < 4; ii++)
                *((float4*)(a_s + (io * 4 + ii) * 132 + jA * 4)) =
                    make_float4(scr[ii][0], scr[ii][1], scr[ii][2], scr[ii][3]);
        }
        __syncthreads();

        // ---- Phase B: 2 rows x 16 j (scalar mix, packed PV) ----
        #pragma unroll 4
        for (int jj = 0; jj < 16; jj++) {
            int j = jh * 16 + jj;
            const ulonglong2* vp = (const ulonglong2*)(v_s + j * 160 + l * 20);
            ulonglong2 va = vp[0], vb = vp[1];
            ulonglong2 vc = vp[2], vd = vp[3];

            float4 aa0 = *((const float4*)(a_s + r0 * 132 + j * 4));
            float4 mk0 = *((const float4*)(m_s + r0 * 132 + j * 4));
            float4 aa1 = *((const float4*)(a_s + (r0 + 1) * 132 + j * 4));
            float4 mk1 = *((const float4*)(m_s + (r0 + 1) * 132 + j * 4));

            float c0 = aa0.x * Tm[0][0] + aa0.y * Tm[0][1] + aa0.z * Tm[0][2] + aa0.w * Tm[0][3];
            float c1 = aa0.x * Tm[1][0] + aa0.y * Tm[1][1] + aa0.z * Tm[1][2] + aa0.w * Tm[1][3];
            float c2 = aa0.x * Tm[2][0] + aa0.y * Tm[2][1] + aa0.z * Tm[2][2] + aa0.w * Tm[2][3];
            float scA = fmaf(mk0.x, c0, SHIFT2) + mk0.y * c1 + mk0.z * c2;

            float d0 = aa1.x * Tm[0][0] + aa1.y * Tm[0][1] + aa1.z * Tm[0][2] + aa1.w * Tm[0][3];
            float d1 = aa1.x * Tm[1][0] + aa1.y * Tm[1][1] + aa1.z * Tm[1][2] + aa1.w * Tm[1][3];
            float d2 = aa1.x * Tm[2][0] + aa1.y * Tm[2][1] + aa1.z * Tm[2][2] + aa1.w * Tm[2][3];
            float scB = fmaf(mk1.x, d0, SHIFT2) + mk1.y * d1 + mk1.z * d2;

            float e0 = exp2f(scA);
            float e1 = exp2f(scB);
            s0 += e0;
            s1 += e1;

            u64 ep0 = pkdup(e0);
            u64 ep1 = pkdup(e1);
            f2(acc0p[0], ep0, va.x); f2(acc0p[1], ep0, va.y);
            f2(acc0p[2], ep0, vb.x); f2(acc0p[3], ep0, vb.y);
            f2(acc0p[4], ep0, vc.x); f2(acc0p[5], ep0, vc.y);
            f2(acc0p[6], ep0, vd.x); f2(acc0p[7], ep0, vd.y);
            f2(acc1p[0], ep1, va.x); f2(acc1p[1], ep1, va.y);
            f2(acc1p[2], ep1, vb.x); f2(acc1p[3], ep1, vb.y);
            f2(acc1p[4], ep1, vc.x); f2(acc1p[5], ep1, vc.y);
            f2(acc1p[6], ep1, vd.x); f2(acc1p[7], ep1, vd.y);
        }
    }

    // unpack accumulators
    float acc0[16], acc1[16];
    #pragma unroll
    for (int d = 0; d < 8; d++) {
        upk(acc0p[d], acc0[2 * d], acc0[2 * d + 1]);
        upk(acc1p[d], acc1[2 * d], acc1[2 * d + 1]);
    }

    // ---- exact cross-jh reduction (fixed-shift softmax = plain sum) ----
    __syncthreads();
    float* red = sm;
    if (jh == 1) {
        float* r = red + (tid - 128) * 36;
        #pragma unroll
        for (int d = 0; d < 16; d++) { r[d] = acc0[d]; r[16 + d] = acc1[d]; }
        r[32] = s0;
        r[33] = s1;
    }
    __syncthreads();
    if (jh == 0) {
        const float* r = red + tid * 36;
        #pragma unroll
        for (int d = 0; d < 16; d++) { acc0[d] += r[d]; acc1[d] += r[16 + d]; }
        s0 += r[32];
        s1 += r[33];

        float inv0 = 1.0f / s0;
        float inv1 = 1.0f / s1;
        float4* o0 = (float4*)(out + ((size_t)(b * NN + i0 + r0))     * 128 + l * 16);
        float4* o1 = (float4*)(out + ((size_t)(b * NN + i0 + r0 + 1)) * 128 + l * 16);
        o0[0] = make_float4(acc0[0]  * inv0, acc0[1]  * inv0, acc0[2]  * inv0, acc0[3]  * inv0);
        o0[1] = make_float4(acc0[4]  * inv0, acc0[5]  * inv0, acc0[6]  * inv0, acc0[7]  * inv0);
        o0[2] = make_float4(acc0[8]  * inv0, acc0[9]  * inv0, acc0[10] * inv0, acc0[11] * inv0);
        o0[3] = make_float4(acc0[12] * inv0, acc0[13] * inv0, acc0[14] * inv0, acc0[15] * inv0);
        o1[0] = make_float4(acc1[0]  * inv1, acc1[1]  * inv1, acc1[2]  * inv1, acc1[3]  * inv1);
        o1[1] = make_float4(acc1[4]  * inv1, acc1[5]  * inv1, acc1[6]  * inv1, acc1[7]  * inv1);
        o1[2] = make_float4(acc1[8]  * inv1, acc1[9]  * inv1, acc1[10] * inv1, acc1[11] * inv1);
        o1[3] = make_float4(acc1[12] * inv1, acc1[13] * inv1, acc1[14] * inv1, acc1[15] * inv1);
    }
}

extern "C" void kernel_launch(void* const* d_in, const int* in_sizes, int n_in,
                              void* d_out, int out_size)
{
    (void)in_sizes; (void)n_in; (void)out_size;
    const float* x     = (const float*)d_in[0];
    const float* masks = (const float*)d_in[1];
    const float* Wq    = (const float*)d_in[2];
    const float* Wk    = (const float*)d_in[3];
    const float* Wv    = (const float*)d_in[4];
    const float* mp    = (const float*)d_in[5];
    float* out = (float*)d_out;

    const size_t smP = (size_t)(128 * 132 + 64 * 128) * sizeof(float);   // 100352 B
    const size_t smA = (size_t)(TI * 68 + TJ * 68 + TJ * 160 + TI * 132 + TI * 132)
                       * sizeof(float);                                  // 71680 B
    cudaFuncSetAttribute(proj_kernel, cudaFuncAttributeMaxDynamicSharedMemorySize, (int)smP);
    cudaFuncSetAttribute(attn_kernel, cudaFuncAttributeMaxDynamicSharedMemorySize, (int)smA);

    proj_kernel<<<dim3(128, 2), 256, smP>>>(x, Wq, Wk, Wv);
    attn_kernel<<<dim3(NN / TI, NB), 256, smA>>>(masks, mp, out);
}